// round 7
// baseline (speedup 1.0000x reference)
#include <cuda_runtime.h>
#include <math.h>

#define DIM    1024
#define HALF   512
#define NMAX   65536
#define P2B    512          // tail blocks (all resident; grid barriers)
#define P2ROWS 128          // rows per tail block in stage A
#define NBPRE  64           // pre blocks

// ---------------- scratch (device globals) ----------------------------------------
__device__ float    g_qpart[NBPRE * HALF];   // Wq GEMV partials
__device__ float    g_qk[DIM];               // Wk @ q
__device__ float    g_s[NMAX];               // raw scores
__device__ float    g_invn[NMAX];            // 1/||k_init[n]||
__device__ float    g_sfA[512];              // score-sum slots
__device__ float    g_sfB[512];              // score-sumsq slots
__device__ float    g_epart[P2B];            // per-block exp sums
__device__ float    g_zpart[P2B * DIM];      // stage-A partial row-sums
__device__ float    g_z[DIM];                // z * invden
__device__ float    g_vpart[P2B * DIM];      // z@Wv partials (2 rows per block)
__device__ float    g_ctx[DIM];              // z@Wv + bv
__device__ float    g_mpart[P2B * DIM];      // ctx@Wm partials
__device__ unsigned g_syncA = 0;             // barrier counter (pre)
__device__ unsigned g_syncB = 0;             // barrier counter (tail)

// ---------------- generation-based grid barrier (all blocks resident) --------------
__device__ __forceinline__ void grid_sync(unsigned* ctr, unsigned nb) {
    __syncthreads();
    if (threadIdx.x == 0) {
        __threadfence();
        unsigned old = atomicAdd(ctr, 1u);
        unsigned target = (old / nb + 1u) * nb;
        while (*(volatile unsigned*)ctr < target) __nanosleep(64);
        __threadfence();
    }
    __syncthreads();
}

// ---------------- 256-thread float2 reduce helper (shuffle tree) -------------------
// in: per-thread float2; out (valid in ALL threads via shared): component-wise sum
__device__ __forceinline__ float2 block_reduce_f2(float2 v, float2* sh8) {
    int t = threadIdx.x, w = t >> 5, l = t & 31;
    #pragma unroll
    for (int o = 16; o; o >>= 1) {
        v.x += __shfl_xor_sync(0xFFFFFFFFu, v.x, o);
        v.y += __shfl_xor_sync(0xFFFFFFFFu, v.y, o);
    }
    if (l == 0) sh8[w] = v;
    __syncthreads();
    float2 r = sh8[0];
    #pragma unroll
    for (int i = 1; i < 8; i++) { r.x += sh8[i].x; r.y += sh8[i].y; }
    return r;
}

// ---------------- kernel 1: q-norm + Wq GEMV + Wk GEMV (64 blocks x 256 thr) ------
__global__ void kern_pre(const float* __restrict__ q_init,
                         const float* __restrict__ Wq,
                         const float* __restrict__ Wk,
                         const float* __restrict__ bq) {
    __shared__ float qn_s[DIM];
    __shared__ float qs[HALF];
    __shared__ float red[8];
    int b = blockIdx.x, t = threadIdx.x, w = t >> 5, l = t & 31;

    // reset stat slots each replay (64 blocks x 8 threads = 512)
    if (t < 8) {
        g_sfA[b * 8 + t] = 0.f;
        g_sfB[b * 8 + t] = 0.f;
    }

    // redundant q l2norm per block (4 KB read, L2 hit)
    float4 v = ((const float4*)q_init)[t];
    float ss = v.x * v.x + v.y * v.y + v.z * v.z + v.w * v.w;
    #pragma unroll
    for (int o = 16; o; o >>= 1) ss += __shfl_xor_sync(0xFFFFFFFFu, ss, o);
    if (l == 0) red[w] = ss;
    __syncthreads();
    if (t == 0) {
        float tot = 0.f;
        #pragma unroll
        for (int i = 0; i < 8; i++) tot += red[i];
        red[0] = 1.0f / fmaxf(sqrtf(tot), 1e-12f);
    }
    __syncthreads();
    float inv = red[0];
    ((float4*)qn_s)[t] = make_float4(v.x * inv, v.y * inv, v.z * inv, v.w * inv);
    __syncthreads();

    // Wq GEMV partial: block b owns d-rows [b*16, b*16+16)
    {
        const float* W = Wq + (size_t)b * 16 * HALF;
        float a0 = 0.f, a1 = 0.f;
        #pragma unroll
        for (int d = 0; d < 16; d++) {
            float x = qn_s[b * 16 + d];
            a0 += x * W[d * HALF + t];
            a1 += x * W[d * HALF + t + 256];
        }
        g_qpart[b * HALF + t]       = a0;
        g_qpart[b * HALF + t + 256] = a1;
    }

    grid_sync(&g_syncA, NBPRE);

    // combine q = bq + sum(partials)
    #pragma unroll
    for (int j = 0; j < 2; j++) {
        int c = t + j * 256;
        float acc = bq[c];
        #pragma unroll 16
        for (int p = 0; p < NBPRE; p++) acc += g_qpart[p * HALF + c];
        qs[c] = acc;
    }
    __syncthreads();

    // Wk GEMV: block b owns qk rows [b*16, b*16+16); 8 warps x 2 rows
    #pragma unroll
    for (int r = 0; r < 2; r++) {
        int d = b * 16 + w * 2 + r;
        const float4* row = (const float4*)(Wk + (size_t)d * HALF);
        const float4* q4  = (const float4*)qs;
        float acc = 0.f;
        #pragma unroll
        for (int i = 0; i < 4; i++) {
            float4 vv = row[i * 32 + l];
            float4 qq = q4[i * 32 + l];
            acc += vv.x * qq.x + vv.y * qq.y + vv.z * qq.z + vv.w * qq.w;
        }
        #pragma unroll
        for (int o = 16; o; o >>= 1) acc += __shfl_xor_sync(0xFFFFFFFFu, acc, o);
        if (l == 0) g_qk[d] = acc;
    }
}

// ---------------- kernel 2: pass 1 over k_init (N/8 blocks x 256 thr) --------------
__global__ void kern_pass1(const float* __restrict__ Kmat) {
    __shared__ float qk_s[DIM];
    int t = threadIdx.x;
    #pragma unroll
    for (int i = 0; i < 4; i++) qk_s[t + i * 256] = g_qk[t + i * 256];
    __syncthreads();
    int w = t >> 5, l = t & 31;
    long n = (long)blockIdx.x * 8 + w;
    const float4* row = (const float4*)(Kmat + n * DIM);
    const float4* q4  = (const float4*)qk_s;
    float ss = 0.f, dp = 0.f;
    #pragma unroll
    for (int i = 0; i < 8; i++) {
        float4 v = row[i * 32 + l];
        float4 q = q4[i * 32 + l];
        ss += v.x * v.x + v.y * v.y + v.z * v.z + v.w * v.w;
        dp += v.x * q.x + v.y * q.y + v.z * q.z + v.w * q.w;
    }
    #pragma unroll
    for (int o = 16; o; o >>= 1) {
        ss += __shfl_xor_sync(0xFFFFFFFFu, ss, o);
        dp += __shfl_xor_sync(0xFFFFFFFFu, dp, o);
    }
    if (l == 0) {
        float inv = 1.0f / fmaxf(sqrtf(ss), 1e-12f);
        float s = dp * inv;
        g_invn[n] = inv;
        g_s[n] = s;
        int slot = (int)(n & 511);
        atomicAdd(&g_sfA[slot], s);
        atomicAdd(&g_sfB[slot], s * s);
    }
}

// ---------------- kernel 3: fused tail (512 blocks x 256 thr, persistent) ----------
// Stage A = pass2 (stats + exp + weighted row-sum partials), then z-reduce,
// Wv GEMV, ctx-reduce, Wm GEMV, out-reduce+gate — all via grid barriers.
__global__ void __launch_bounds__(256, 4)
kern_tail(const float* __restrict__ Kmat,
          const float* __restrict__ Wv,
          const float* __restrict__ Wm,
          const float* __restrict__ bv,
          const float* __restrict__ bm,
          const float* __restrict__ q_init,
          const float* __restrict__ gamma,
          float* __restrict__ out,
          int N) {
    __shared__ float  ws[P2ROWS];
    __shared__ float  st[2];
    __shared__ float2 sh8[8];
    __shared__ float  redA[8];
    __shared__ float  redB[8];
    int b = blockIdx.x, t = threadIdx.x, w = t >> 5, l = t & 31;

    // ===== Stage A: pass 2 (reversed rows for L2 reuse of pass-1 tail) =====
    {
        long n0 = (long)(P2B - 1 - b) * P2ROWS;

        // finalize stats (redundant per block; 4 KB of L2-hit reads)
        float sa = g_sfA[t] + g_sfA[t + 256];
        float sb = g_sfB[t] + g_sfB[t + 256];
        #pragma unroll
        for (int o = 16; o; o >>= 1) {
            sa += __shfl_xor_sync(0xFFFFFFFFu, sa, o);
            sb += __shfl_xor_sync(0xFFFFFFFFu, sb, o);
        }
        if (l == 0) { redA[w] = sa; redB[w] = sb; }
        __syncthreads();
        if (t == 0) {
            float A = 0.f, B = 0.f;
            #pragma unroll
            for (int i = 0; i < 8; i++) { A += redA[i]; B += redB[i]; }
            double mean = (double)A / N;
            double var  = ((double)B - (double)N * mean * mean) / (double)(N - 1);
            double sd   = sqrt(var > 0.0 ? var : 0.0);
            st[0] = (float)mean;
            st[1] = (float)(1.0 / (sd + 1e-8));
        }
        __syncthreads();
        float mean = st[0], rstd = st[1];

        float e = 0.f;
        if (t < P2ROWS) {
            float s   = g_s[n0 + t];
            float inv = g_invn[n0 + t];
            float x = fminf(fmaxf((s - mean) * rstd, -10.f), 10.f);
            e = expf(x);
            ws[t] = e * inv;
        }
        #pragma unroll
        for (int o = 16; o; o >>= 1) e += __shfl_xor_sync(0xFFFFFFFFu, e, o);
        if (l == 0) redA[w] = e;
        __syncthreads();
        if (t == 0) {
            float tot = 0.f;
            #pragma unroll
            for (int i = 0; i < 4; i++) tot += redA[i];
            g_epart[b] = tot;
        }
        __syncthreads();

        float4 acc = make_float4(0.f, 0.f, 0.f, 0.f);
        const float4* base = (const float4*)Kmat + n0 * (DIM / 4) + t;
        #pragma unroll 8
        for (int r = 0; r < P2ROWS; r++) {
            float wv = ws[r];
            float4 v = base[(long)r * (DIM / 4)];
            acc.x += wv * v.x;
            acc.y += wv * v.y;
            acc.z += wv * v.z;
            acc.w += wv * v.w;
        }
        ((float4*)g_zpart)[b * (DIM / 4) + t] = acc;
    }

    grid_sync(&g_syncB, P2B);

    // ===== Stage B: z[2b],z[2b+1] = invden * sum_p zpart[p][2b..2b+1] =====
    {
        const float2* zp = (const float2*)g_zpart;
        float2 v0 = zp[(size_t)t * HALF + b];
        float2 v1 = zp[(size_t)(t + 256) * HALF + b];
        float2 s2 = make_float2(v0.x + v1.x, v0.y + v1.y);
        // epart sum folded into same reduce window
        float e = g_epart[t] + g_epart[t + 256];
        #pragma unroll
        for (int o = 16; o; o >>= 1) e += __shfl_xor_sync(0xFFFFFFFFu, e, o);
        if (l == 0) redA[w] = e;
        float2 z2 = block_reduce_f2(s2, sh8);
        if (t == 0) {
            float den = 0.f;
            #pragma unroll
            for (int i = 0; i < 8; i++) den += redA[i];
            float invden = 1.0f / den;
            ((float2*)g_z)[b] = make_float2(z2.x * invden, z2.y * invden);
        }
    }

    grid_sync(&g_syncB, P2B);

    // ===== Stage C: Wv GEMV rows {2b, 2b+1} -> vpart[b][:] =====
    {
        float2 zz = ((const float2*)g_z)[b];
        const float4* r0 = (const float4*)(Wv + (size_t)(2 * b) * DIM);
        const float4* r1 = r0 + (DIM / 4);
        float4 a0 = r0[t], a1 = r1[t];
        float4 acc;
        acc.x = zz.x * a0.x + zz.y * a1.x;
        acc.y = zz.x * a0.y + zz.y * a1.y;
        acc.z = zz.x * a0.z + zz.y * a1.z;
        acc.w = zz.x * a0.w + zz.y * a1.w;
        ((float4*)g_vpart)[b * (DIM / 4) + t] = acc;
    }

    grid_sync(&g_syncB, P2B);

    // ===== Stage D: ctx[2b],ctx[2b+1] = bv + sum_p vpart[p][2b..2b+1] =====
    {
        const float2* vp = (const float2*)g_vpart;
        float2 v0 = vp[(size_t)t * HALF + b];
        float2 v1 = vp[(size_t)(t + 256) * HALF + b];
        float2 s2 = make_float2(v0.x + v1.x, v0.y + v1.y);
        float2 c2 = block_reduce_f2(s2, sh8);
        if (t == 0) {
            float2 bb = ((const float2*)bv)[b];
            ((float2*)g_ctx)[b] = make_float2(c2.x + bb.x, c2.y + bb.y);
        }
    }

    grid_sync(&g_syncB, P2B);

    // ===== Stage E: Wm GEMV rows {2b, 2b+1} -> mpart[b][:] =====
    {
        float2 cc = ((const float2*)g_ctx)[b];
        const float4* r0 = (const float4*)(Wm + (size_t)(2 * b) * DIM);
        const float4* r1 = r0 + (DIM / 4);
        float4 a0 = r0[t], a1 = r1[t];
        float4 acc;
        acc.x = cc.x * a0.x + cc.y * a1.x;
        acc.y = cc.x * a0.y + cc.y * a1.y;
        acc.z = cc.x * a0.z + cc.y * a1.z;
        acc.w = cc.x * a0.w + cc.y * a1.w;
        ((float4*)g_mpart)[b * (DIM / 4) + t] = acc;
    }

    grid_sync(&g_syncB, P2B);

    // ===== Stage F: out[2b],out[2b+1] = gate(q_init, mpart-reduce + bm) =====
    {
        const float2* mp = (const float2*)g_mpart;
        float2 v0 = mp[(size_t)t * HALF + b];
        float2 v1 = mp[(size_t)(t + 256) * HALF + b];
        float2 s2 = make_float2(v0.x + v1.x, v0.y + v1.y);
        float2 m2 = block_reduce_f2(s2, sh8);
        if (t == 0) {
            float2 bb = ((const float2*)bm)[b];
            float2 qq = ((const float2*)q_init)[b];
            float gg = 1.0f / (1.0f + expf(-gamma[0]));
            float2 o2;
            o2.x = gg * qq.x + (1.0f - gg) * (m2.x + bb.x);
            o2.y = gg * qq.y + (1.0f - gg) * (m2.y + bb.y);
            ((float2*)out)[b] = o2;
        }
    }
}

// ---------------- launcher ----------------------------------------------------------
extern "C" void kernel_launch(void* const* d_in, const int* in_sizes, int n_in,
                              void* d_out, int out_size) {
    const float* q_init = (const float*)d_in[0];
    const float* k_init = (const float*)d_in[1];
    const float* Wq     = (const float*)d_in[2];
    const float* bq     = (const float*)d_in[3];
    const float* Wk     = (const float*)d_in[4];
    // d_in[5] = bk: cancels under z-score normalization of scores
    const float* Wv     = (const float*)d_in[6];
    const float* bv     = (const float*)d_in[7];
    const float* Wm     = (const float*)d_in[8];
    const float* bm     = (const float*)d_in[9];
    const float* gamma  = (const float*)d_in[10];
    float* out = (float*)d_out;

    int N = in_sizes[1] / DIM;  // 65536

    kern_pre  <<<NBPRE, 256>>>(q_init, Wq, Wk, bq);
    kern_pass1<<<N / 8, 256>>>(k_init);
    kern_tail <<<P2B, 256>>>(k_init, Wv, Wm, bv, bm, q_init, gamma, out, N);
}

// round 8
// speedup vs baseline: 1.0468x; 1.0468x over previous
#include <cuda_runtime.h>
#include <math.h>

#define DIM    1024
#define HALF   512
#define NMAX   65536
#define P2B    512          // pass2 blocks
#define P2ROWS 128          // rows per pass2 block
#define NBPRE  64           // pre-blocks inside pass1
#define NBPOST 128          // post blocks

// ---------------- scratch (device globals) ----------------------------------------
__device__ float    g_qpart[NBPRE * HALF];   // Wq GEMV partials
__device__ float    g_qk[DIM];               // Wk @ q
__device__ float    g_s[NMAX];               // raw scores
__device__ float    g_invn[NMAX];            // 1/||k_init[n]||
__device__ float    g_sfA[512];              // score-sum slots
__device__ float    g_sfB[512];              // score-sumsq slots
__device__ float    g_epart[P2B];            // per-pass2-block exp sums
__device__ float    g_zpart[P2B * DIM];      // pass2 partial row-sums
__device__ float    g_vpart[NBPOST * DIM];   // z@Wv partials
__device__ float    g_mpart[NBPOST * DIM];   // ctx@Wm partials
__device__ unsigned g_syncA = 0;             // generation barrier (pre blocks)
__device__ unsigned g_syncB = 0;             // generation barrier (post)
__device__ unsigned g_qkdone = 0;            // qk-ready flag (reset by pass2)

// ---------------- generation-based grid barrier (participants resident) ------------
__device__ __forceinline__ void grid_sync(unsigned* ctr, unsigned nb) {
    __syncthreads();
    if (threadIdx.x == 0) {
        __threadfence();
        unsigned old = atomicAdd(ctr, 1u);
        unsigned target = (old / nb + 1u) * nb;
        while (*(volatile unsigned*)ctr < target) __nanosleep(64);
        __threadfence();
    }
    __syncthreads();
}

// ---------------- kernel 1: fused pre + pass 1 (N/8 blocks x 256 thr) --------------
// Blocks 0..63 compute qk = Wk @ (l2norm(q_init) @ Wq + bq) first, then flag.
// ALL blocks: load their 8 K rows into registers + compute norms (overlaps with
// pre), poll the flag, then finish the score dot-products from registers.
__global__ void __launch_bounds__(256, 4)
kern_pass1(const float* __restrict__ Kmat,
           const float* __restrict__ q_init,
           const float* __restrict__ Wq,
           const float* __restrict__ Wk,
           const float* __restrict__ bq) {
    __shared__ float sh[DIM + HALF];   // pre: qn|qs ; pass1: qk
    __shared__ float red[8];
    int b = blockIdx.x, t = threadIdx.x, w = t >> 5, l = t & 31;

    // ===================== pre (blocks 0..63 only) =====================
    if (b < NBPRE) {
        // reset stat slots each replay (64 blocks x 8 threads = 512)
        if (t < 8) {
            g_sfA[b * 8 + t] = 0.f;
            g_sfB[b * 8 + t] = 0.f;
        }

        // q l2norm (redundant per pre-block; 4 KB, L2 hit)
        float4 v = ((const float4*)q_init)[t];
        float ss = v.x * v.x + v.y * v.y + v.z * v.z + v.w * v.w;
        #pragma unroll
        for (int o = 16; o; o >>= 1) ss += __shfl_xor_sync(0xFFFFFFFFu, ss, o);
        if (l == 0) red[w] = ss;
        __syncthreads();
        if (t == 0) {
            float tot = 0.f;
            #pragma unroll
            for (int i = 0; i < 8; i++) tot += red[i];
            red[0] = 1.0f / fmaxf(sqrtf(tot), 1e-12f);
        }
        __syncthreads();
        float inv = red[0];
        ((float4*)sh)[t] = make_float4(v.x * inv, v.y * inv, v.z * inv, v.w * inv);
        __syncthreads();

        // Wq GEMV partial: pre-block b owns d-rows [b*16, b*16+16)
        {
            const float* W = Wq + (size_t)b * 16 * HALF;
            float a0 = 0.f, a1 = 0.f;
            #pragma unroll
            for (int d = 0; d < 16; d++) {
                float x = sh[b * 16 + d];
                a0 += x * W[d * HALF + t];
                a1 += x * W[d * HALF + t + 256];
            }
            g_qpart[b * HALF + t]       = a0;
            g_qpart[b * HALF + t + 256] = a1;
        }

        grid_sync(&g_syncA, NBPRE);   // among the 64 pre blocks (wave-1 resident)

        // combine q = bq + sum(partials) into sh[DIM..DIM+HALF)
        #pragma unroll
        for (int j = 0; j < 2; j++) {
            int c = t + j * 256;
            float acc = bq[c];
            #pragma unroll 16
            for (int p = 0; p < NBPRE; p++) acc += g_qpart[p * HALF + c];
            sh[DIM + c] = acc;
        }
        __syncthreads();

        // Wk GEMV: pre-block b owns qk rows [b*16, b*16+16); 8 warps x 2 rows
        #pragma unroll
        for (int r = 0; r < 2; r++) {
            int d = b * 16 + w * 2 + r;
            const float4* row = (const float4*)(Wk + (size_t)d * HALF);
            const float4* q4  = (const float4*)(sh + DIM);
            float acc = 0.f;
            #pragma unroll
            for (int i = 0; i < 4; i++) {
                float4 vv = row[i * 32 + l];
                float4 qq = q4[i * 32 + l];
                acc += vv.x * qq.x + vv.y * qq.y + vv.z * qq.z + vv.w * qq.w;
            }
            #pragma unroll
            for (int o = 16; o; o >>= 1) acc += __shfl_xor_sync(0xFFFFFFFFu, acc, o);
            if (l == 0) g_qk[d] = acc;
        }
        __syncthreads();
        if (t == 0) {
            __threadfence();
            atomicAdd(&g_qkdone, 1u);
        }
    }

    // ===================== pass 1 (all blocks) =====================
    long n = (long)b * 8 + w;
    const float4* rowp = (const float4*)(Kmat + n * DIM);

    // load 8 float4 into registers; norm does not depend on qk
    float4 v0 = rowp[l],        v1 = rowp[32 + l],  v2 = rowp[64 + l],  v3 = rowp[96 + l];
    float4 v4 = rowp[128 + l],  v5 = rowp[160 + l], v6 = rowp[192 + l], v7 = rowp[224 + l];

    float ss = v0.x*v0.x + v0.y*v0.y + v0.z*v0.z + v0.w*v0.w
             + v1.x*v1.x + v1.y*v1.y + v1.z*v1.z + v1.w*v1.w
             + v2.x*v2.x + v2.y*v2.y + v2.z*v2.z + v2.w*v2.w
             + v3.x*v3.x + v3.y*v3.y + v3.z*v3.z + v3.w*v3.w
             + v4.x*v4.x + v4.y*v4.y + v4.z*v4.z + v4.w*v4.w
             + v5.x*v5.x + v5.y*v5.y + v5.z*v5.z + v5.w*v5.w
             + v6.x*v6.x + v6.y*v6.y + v6.z*v6.z + v6.w*v6.w
             + v7.x*v7.x + v7.y*v7.y + v7.z*v7.z + v7.w*v7.w;
    #pragma unroll
    for (int o = 16; o; o >>= 1) ss += __shfl_xor_sync(0xFFFFFFFFu, ss, o);
    float inv = 1.0f / fmaxf(sqrtf(ss), 1e-12f);
    if (l == 0) g_invn[n] = inv;

    // wait until qk is ready (overlapped with the loads above)
    if (t == 0) {
        while (*(volatile unsigned*)&g_qkdone < (unsigned)NBPRE) __nanosleep(64);
    }
    __syncthreads();

    // qk into shared (first access on this SM this launch -> no stale L1)
    #pragma unroll
    for (int i = 0; i < 4; i++) sh[t + i * 256] = g_qk[t + i * 256];
    __syncthreads();

    const float4* q4 = (const float4*)sh;
    float4 q;
    float dp = 0.f;
    q = q4[l];        dp += v0.x*q.x + v0.y*q.y + v0.z*q.z + v0.w*q.w;
    q = q4[32 + l];   dp += v1.x*q.x + v1.y*q.y + v1.z*q.z + v1.w*q.w;
    q = q4[64 + l];   dp += v2.x*q.x + v2.y*q.y + v2.z*q.z + v2.w*q.w;
    q = q4[96 + l];   dp += v3.x*q.x + v3.y*q.y + v3.z*q.z + v3.w*q.w;
    q = q4[128 + l];  dp += v4.x*q.x + v4.y*q.y + v4.z*q.z + v4.w*q.w;
    q = q4[160 + l];  dp += v5.x*q.x + v5.y*q.y + v5.z*q.z + v5.w*q.w;
    q = q4[192 + l];  dp += v6.x*q.x + v6.y*q.y + v6.z*q.z + v6.w*q.w;
    q = q4[224 + l];  dp += v7.x*q.x + v7.y*q.y + v7.z*q.z + v7.w*q.w;
    #pragma unroll
    for (int o = 16; o; o >>= 1) dp += __shfl_xor_sync(0xFFFFFFFFu, dp, o);

    if (l == 0) {
        float s = dp * inv;
        g_s[n] = s;
        int slot = (int)(n & 511);
        atomicAdd(&g_sfA[slot], s);
        atomicAdd(&g_sfB[slot], s * s);
    }
}

// ---------------- kernel 2: pass 2 with fused exp (P2B blocks x 256 thr) -----------
// reversed row order: consume the L2-resident tail of K left by pass 1 first
__global__ void kern_pass2(const float* __restrict__ Kmat, int N) {
    __shared__ float ws[P2ROWS];
    __shared__ float st[2];    // mean, rstd
    __shared__ float redA[8];
    __shared__ float redB[8];
    int t = threadIdx.x, w = t >> 5, l = t & 31;
    long n0 = (long)(P2B - 1 - blockIdx.x) * P2ROWS;

    if (blockIdx.x == 0 && t == 0) g_qkdone = 0;   // reset flag for next replay

    // finalize stats (redundant per block; 4 KB of L2-hit reads)
    {
        float sa = g_sfA[t] + g_sfA[t + 256];
        float sb = g_sfB[t] + g_sfB[t + 256];
        #pragma unroll
        for (int o = 16; o; o >>= 1) {
            sa += __shfl_xor_sync(0xFFFFFFFFu, sa, o);
            sb += __shfl_xor_sync(0xFFFFFFFFu, sb, o);
        }
        if (l == 0) { redA[w] = sa; redB[w] = sb; }
        __syncthreads();
        if (t == 0) {
            float A = 0.f, B = 0.f;
            #pragma unroll
            for (int i = 0; i < 8; i++) { A += redA[i]; B += redB[i]; }
            double mean = (double)A / N;
            double var  = ((double)B - (double)N * mean * mean) / (double)(N - 1);
            double sd   = sqrt(var > 0.0 ? var : 0.0);
            st[0] = (float)mean;
            st[1] = (float)(1.0 / (sd + 1e-8));
        }
        __syncthreads();
    }
    float mean = st[0], rstd = st[1];

    // this block's 128 weights: w = exp(clip(zscore)) * invn ; e-sum to g_epart
    float e = 0.f;
    if (t < P2ROWS) {
        float s   = g_s[n0 + t];
        float inv = g_invn[n0 + t];
        float x = fminf(fmaxf((s - mean) * rstd, -10.f), 10.f);
        e = expf(x);
        ws[t] = e * inv;
    }
    #pragma unroll
    for (int o = 16; o; o >>= 1) e += __shfl_xor_sync(0xFFFFFFFFu, e, o);
    if (l == 0) redA[w] = e;
    __syncthreads();
    if (t == 0) {
        float tot = 0.f;
        #pragma unroll
        for (int i = 0; i < 4; i++) tot += redA[i];   // warps 4..7 hold zeros
        g_epart[blockIdx.x] = tot;
    }
    __syncthreads();

    // weighted row-sum partials (1/denom deferred to kern_post)
    float4 acc = make_float4(0.f, 0.f, 0.f, 0.f);
    const float4* base = (const float4*)Kmat + n0 * (DIM / 4) + t;
    #pragma unroll 8
    for (int r = 0; r < P2ROWS; r++) {
        float wv = ws[r];
        float4 v = base[(long)r * (DIM / 4)];
        acc.x += wv * v.x;
        acc.y += wv * v.y;
        acc.z += wv * v.z;
        acc.w += wv * v.w;
    }
    ((float4*)g_zpart)[blockIdx.x * (DIM / 4) + t] = acc;
}

// ---------------- kernel 3: z-reduce + Wv GEMV + Wm GEMV + gate (128 x 256) --------
__global__ void kern_post(const float* __restrict__ Wv,
                          const float* __restrict__ Wm,
                          const float* __restrict__ bv,
                          const float* __restrict__ bm,
                          const float* __restrict__ q_init,
                          const float* __restrict__ gamma,
                          float* __restrict__ out) {
    __shared__ float cred[8][33];
    __shared__ float xs[8];
    __shared__ float red[8];
    __shared__ float invden_s;
    int b = blockIdx.x, t = threadIdx.x, w = t >> 5, l = t & 31;
    int j = t & 7, g = t >> 3;   // 8 cols x 32 groups

    // fused phase: denom partials + z-partial reduction in one load window
    {
        float e2 = g_epart[t] + g_epart[t + 256];
        float a = 0.f;
        #pragma unroll
        for (int k = 0; k < 16; k++)
            a += g_zpart[(g * 16 + k) * DIM + b * 8 + j];
        #pragma unroll
        for (int o = 16; o; o >>= 1) e2 += __shfl_xor_sync(0xFFFFFFFFu, e2, o);
        if (l == 0) red[w] = e2;
        cred[j][g] = a;
        __syncthreads();
        if (t == 0) {
            float tot = 0.f;
            #pragma unroll
            for (int i = 0; i < 8; i++) tot += red[i];
            invden_s = 1.0f / tot;
        }
        if (t < 8) {
            float s = 0.f;
            #pragma unroll
            for (int i = 0; i < 32; i++) s += cred[t][i];
            xs[t] = s;            // invden folded into GEMV below
        }
        __syncthreads();
    }
    float invden = invden_s;

    // Wv GEMV partial from z slice (8 d-rows), invden folded in
    {
        const float4* W4 = (const float4*)(Wv + (size_t)b * 8 * DIM) + t;
        float4 acc = make_float4(0.f, 0.f, 0.f, 0.f);
        #pragma unroll
        for (int d = 0; d < 8; d++) {
            float xv = xs[d] * invden;
            float4 v = W4[d * (DIM / 4)];
            acc.x += xv * v.x;
            acc.y += xv * v.y;
            acc.z += xv * v.z;
            acc.w += xv * v.w;
        }
        ((float4*)g_vpart)[b * (DIM / 4) + t] = acc;
    }

    grid_sync(&g_syncB, NBPOST);

    // ctx slice: bv + reduce of 128 v-partials over cols [b*8, b*8+8)
    {
        float a = 0.f;
        #pragma unroll
        for (int k = 0; k < 4; k++)
            a += g_vpart[(g * 4 + k) * DIM + b * 8 + j];
        cred[j][g] = a;
        __syncthreads();
        if (t < 8) {
            float s = bv[b * 8 + t];
            #pragma unroll
            for (int i = 0; i < 32; i++) s += cred[t][i];
            xs[t] = s;
        }
        __syncthreads();
    }

    // Wm GEMV partial from ctx slice
    {
        const float4* W4 = (const float4*)(Wm + (size_t)b * 8 * DIM) + t;
        float4 acc = make_float4(0.f, 0.f, 0.f, 0.f);
        #pragma unroll
        for (int d = 0; d < 8; d++) {
            float xv = xs[d];
            float4 v = W4[d * (DIM / 4)];
            acc.x += xv * v.x;
            acc.y += xv * v.y;
            acc.z += xv * v.z;
            acc.w += xv * v.w;
        }
        ((float4*)g_mpart)[b * (DIM / 4) + t] = acc;
    }

    grid_sync(&g_syncB, NBPOST);

    // final gate for out cols [b*8, b*8+8)
    {
        float a = 0.f;
        #pragma unroll
        for (int k = 0; k < 4; k++)
            a += g_mpart[(g * 4 + k) * DIM + b * 8 + j];
        cred[j][g] = a;
        __syncthreads();
        if (t < 8) {
            int c = b * 8 + t;
            float s = bm[c];
            #pragma unroll
            for (int i = 0; i < 32; i++) s += cred[t][i];
            float gg = 1.0f / (1.0f + expf(-gamma[0]));
            out[c] = gg * q_init[c] + (1.0f - gg) * s;
        }
    }
}

// ---------------- launcher ----------------------------------------------------------
extern "C" void kernel_launch(void* const* d_in, const int* in_sizes, int n_in,
                              void* d_out, int out_size) {
    const float* q_init = (const float*)d_in[0];
    const float* k_init = (const float*)d_in[1];
    const float* Wq     = (const float*)d_in[2];
    const float* bq     = (const float*)d_in[3];
    const float* Wk     = (const float*)d_in[4];
    // d_in[5] = bk: cancels under z-score normalization of scores
    const float* Wv     = (const float*)d_in[6];
    const float* bv     = (const float*)d_in[7];
    const float* Wm     = (const float*)d_in[8];
    const float* bm     = (const float*)d_in[9];
    const float* gamma  = (const float*)d_in[10];
    float* out = (float*)d_out;

    int N = in_sizes[1] / DIM;  // 65536

    kern_pass1<<<N / 8, 256>>>(k_init, q_init, Wq, Wk, bq);
    kern_pass2<<<P2B, 256>>>(k_init, N);
    kern_post <<<NBPOST, 256>>>(Wv, Wm, bv, bm, q_init, gamma, out);
}